// round 11
// baseline (speedup 1.0000x reference)
#include <cuda_runtime.h>
#include <cuda_bf16.h>
#include <cuda_fp16.h>
#include <math.h>

#define NN 8192
#define DD 64
#define EE 262144
#define HSIZE (1u << 19)
#define HMASK (HSIZE - 1u)
#define HEMPTY 0xFFFFFFFFFFFFFFFFull

// ===================== base-ISA tensor primitives =====================
#define MMA_BF16(C, A, B0, B1) \
    asm volatile("mma.sync.aligned.m16n8k16.row.col.f32.bf16.bf16.f32 " \
        "{%0,%1,%2,%3}, {%4,%5,%6,%7}, {%8,%9}, {%0,%1,%2,%3};" \
        : "+f"((C)[0]), "+f"((C)[1]), "+f"((C)[2]), "+f"((C)[3]) \
        : "r"((A)[0]), "r"((A)[1]), "r"((A)[2]), "r"((A)[3]), "r"(B0), "r"(B1))

#define MMA_F16(C, A, B0, B1) \
    asm volatile("mma.sync.aligned.m16n8k16.row.col.f32.f16.f16.f32 " \
        "{%0,%1,%2,%3}, {%4,%5,%6,%7}, {%8,%9}, {%0,%1,%2,%3};" \
        : "+f"((C)[0]), "+f"((C)[1]), "+f"((C)[2]), "+f"((C)[3]) \
        : "r"((A)[0]), "r"((A)[1]), "r"((A)[2]), "r"((A)[3]), "r"(B0), "r"(B1))

#define LDSM4(R, addr) \
    asm volatile("ldmatrix.sync.aligned.m8n8.x4.shared.b16 {%0,%1,%2,%3}, [%4];" \
        : "=r"((R)[0]), "=r"((R)[1]), "=r"((R)[2]), "=r"((R)[3]) : "r"(addr))

#define CPA16(dst, src) \
    asm volatile("cp.async.cg.shared.global [%0], [%1], 16;" :: "r"(dst), "l"(src))
#define CP_COMMIT() asm volatile("cp.async.commit_group;" ::: "memory")
#define CP_WAIT0()  asm volatile("cp.async.wait_group 0;" ::: "memory")

__device__ __forceinline__ unsigned pack_bf16x2(float lo, float hi) {
    unsigned r;
    asm("cvt.rn.bf16x2.f32 %0, %1, %2;" : "=r"(r) : "f"(hi), "f"(lo));
    return r;
}

// ===================== static device scratch =====================
__device__ float g_G[NN * 128];                 // fp32 G (corr exact scores)
__device__ __half g_Gh[NN * 128];               // fp16 G (S matmul)
__device__ __nv_bfloat16 g_Vth[128 * NN];       // V^T bf16 (PV matmul)
__device__ float g_ediag[NN];                   // exp(||mag_i||^2)
__device__ float g_rsum[NN];
__device__ float g_accm[NN * DD];
__device__ float g_accp[NN * DD];
__device__ unsigned long long g_hash[HSIZE];
__device__ float g_escore[EE];
__device__ int   g_ne;
__device__ int   g_csrc[EE];
__device__ int   g_cdst[EE];
__device__ float g_cbias[EE];
__device__ float g_wsum4[4];
__device__ float g_bsum;
__device__ int   g_idx64;

// ===================== small kernels =====================
// wsum reduction + edge_index dtype detect (fused)
__global__ void k_wsum(const float* __restrict__ W, const float* __restrict__ b,
                       const unsigned* __restrict__ ei) {
    __shared__ float red[5][64];
    int t = threadIdx.x;
    red[0][t] = W[t * 4 + 0];
    red[1][t] = W[t * 4 + 1];
    red[2][t] = W[t * 4 + 2];
    red[3][t] = W[t * 4 + 3];
    red[4][t] = b[t];
    __syncthreads();
    if (t < 5) {
        float s = 0.f;
        #pragma unroll
        for (int i = 0; i < 64; i++) s += red[t][i];
        if (t < 4) g_wsum4[t] = s;
        else       g_bsum = s;
    }
    if (t == 0) {
        int all0 = 1;
        #pragma unroll
        for (int i = 1; i < 64; i += 2)
            if (ei[i] != 0u) all0 = 0;
        g_idx64 = all0;
    }
}

// G build + ediag (fused, warp per row)
__global__ void k_prep(const float* __restrict__ mag, const float* __restrict__ phase) {
    int w = (blockIdx.x * blockDim.x + threadIdx.x) >> 5;   // row
    int lane = threadIdx.x & 31;
    float2 m  = *(const float2*)(mag + w * 64 + lane * 2);
    float2 ph = *(const float2*)(phase + w * 64 + lane * 2);
    float s0, c0, s1, c1;
    sincosf(ph.x, &s0, &c0);
    sincosf(ph.y, &s1, &c1);
    float gc0 = m.x * c0, gc1 = m.y * c1, gs0 = m.x * s0, gs1 = m.y * s1;
    *(float2*)(g_G + w * 128 + lane * 2)      = make_float2(gc0, gc1);
    *(float2*)(g_G + w * 128 + 64 + lane * 2) = make_float2(gs0, gs1);
    __half2* gh = (__half2*)(g_Gh + w * 128);
    gh[lane]      = __floats2half2_rn(gc0, gc1);
    gh[32 + lane] = __floats2half2_rn(gs0, gs1);
    float s = m.x * m.x + m.y * m.y;
    #pragma unroll
    for (int o = 16; o; o >>= 1) s += __shfl_xor_sync(0xffffffffu, s, o);
    if (lane == 0) g_ediag[w] = __expf(s);
}

// transpose [k][d] -> Vt[d][k] bf16 (32x32 tiles)
__global__ void k_prepv(const float* __restrict__ mag, const float* __restrict__ phase) {
    __shared__ float t[32][33];
    int k0 = blockIdx.x * 32;
    int d0 = blockIdx.y * 32;
    int tx = threadIdx.x & 31, ty = threadIdx.x >> 5;
    const float* src = (d0 < 64) ? mag : phase;
    int dcol = (d0 < 64) ? d0 : d0 - 64;
    #pragma unroll
    for (int r = 0; r < 4; r++) {
        int k = k0 + ty + r * 8;
        t[ty + r * 8][tx] = src[k * 64 + dcol + tx];
    }
    __syncthreads();
    #pragma unroll
    for (int r = 0; r < 4; r++) {
        int d = d0 + ty + r * 8;
        g_Vth[d * NN + k0 + tx] = __float2bfloat16(t[tx][ty + r * 8]);
    }
}

// ---- edge scores + lock-free dedupe (last edge index wins) ----
__global__ void k_edge(const void* __restrict__ eiv, const float* __restrict__ ea) {
    int e = blockIdx.x * blockDim.x + threadIdx.x;
    if (e >= EE) return;
    int src, dst;
    if (g_idx64) {
        const long long* ei = (const long long*)eiv;
        src = (int)ei[e];
        dst = (int)ei[EE + e];
    } else {
        const int* ei = (const int*)eiv;
        src = ei[e];
        dst = ei[EE + e];
    }
    src &= 8191; dst &= 8191;

    float score = ea[4 * e + 0] * g_wsum4[0] + ea[4 * e + 1] * g_wsum4[1]
                + ea[4 * e + 2] * g_wsum4[2] + ea[4 * e + 3] * g_wsum4[3] + g_bsum;
    g_escore[e] = score;

    unsigned key = ((unsigned)src << 13) | (unsigned)dst;
    unsigned long long entry = ((unsigned long long)key << 32) | (unsigned)e;
    unsigned h = key * 0x9E3779B1u;
    h ^= h >> 15;
    h &= HMASK;
    for (;;) {
        unsigned long long cur = g_hash[h];
        if (cur == HEMPTY) {
            unsigned long long prev = atomicCAS(&g_hash[h], HEMPTY, entry);
            if (prev == HEMPTY) break;
            cur = prev;
        }
        if ((unsigned)(cur >> 32) == key) {
            atomicMax(&g_hash[h], entry);
            break;
        }
        h = (h + 1) & HMASK;
    }
}

__global__ void k_compact() {
    unsigned idx = blockIdx.x * blockDim.x + threadIdx.x;
    if (idx >= HSIZE) return;
    unsigned long long cur = g_hash[idx];
    if (cur == HEMPTY) return;
    unsigned key = (unsigned)(cur >> 32);
    unsigned e   = (unsigned)(cur & 0xFFFFFFFFu);
    int pos = atomicAdd(&g_ne, 1);
    g_csrc[pos]  = (int)(key >> 13);
    g_cdst[pos]  = (int)(key & 8191u);
    g_cbias[pos] = g_escore[e];
}

// ===================== fused main kernel =====================
// grid 512: bid<256 -> flash attention (qb=bid>>2, ks=bid&3, 2048 keys each);
//           bid>=256 -> sparse bias corrections (grid-stride over deduped edges).
// Corr CTAs backfill SM slots the attention wave leaves idle; their L2/atomic
// traffic doesn't contend with the saturated HMMA pipe.
#define QSTR 272
#define VSTR 144
#define SQH  0
#define BUF0 34816
#define BUFS 35840
#define KH_O 0
#define VH_O 17408
#define SMEMSZ (BUF0 + 2 * BUFS)   // 106496
#define NITER 32
#define ATTN_CTAS 256
#define CORR_CTAS 256

__device__ __forceinline__ void corr_work(const float* __restrict__ mag,
                                          const float* __restrict__ phase) {
    int lane = threadIdx.x & 31;
    int wid = threadIdx.x >> 5;
    int ne = g_ne;
    for (int w = ((int)blockIdx.x - ATTN_CTAS) * 8 + wid; w < ne; w += CORR_CTAS * 8) {
        int src = g_csrc[w], dst = g_cdst[w];
        float bias = g_cbias[w];

        const float4* Gs = (const float4*)(g_G + src * 128);
        const float4* Gd = (const float4*)(g_G + dst * 128);
        float4 a = Gs[lane], q = Gd[lane];
        float s = a.x * q.x + a.y * q.y + a.z * q.z + a.w * q.w;
        #pragma unroll
        for (int off = 16; off; off >>= 1) s += __shfl_xor_sync(0xffffffffu, s, off);

        float delta = __expf(s) * expm1f(bias);
        if (fabsf(delta) <= 3e-7f * g_ediag[src]) continue;   // uniform across warp

        if (lane == 0) atomicAdd(&g_rsum[src], delta);
        atomicAdd(&g_accm[src * 64 + lane],      delta * mag[dst * 64 + lane]);
        atomicAdd(&g_accm[src * 64 + lane + 32], delta * mag[dst * 64 + lane + 32]);
        atomicAdd(&g_accp[src * 64 + lane],      delta * phase[dst * 64 + lane]);
        atomicAdd(&g_accp[src * 64 + lane + 32], delta * phase[dst * 64 + lane + 32]);
    }
}

__global__ void __launch_bounds__(256, 2)
k_main(const float* __restrict__ mag, const float* __restrict__ phase) {
    if (blockIdx.x >= ATTN_CTAS) {
        corr_work(mag, phase);
        return;
    }

    extern __shared__ __align__(1024) char smem[];
    unsigned sb;
    asm("{ .reg .u64 t; cvta.to.shared.u64 t, %1; cvt.u32.u64 %0, t; }"
        : "=r"(sb) : "l"(smem));

    const int tid = threadIdx.x;
    const int lane = tid & 31;
    const int wid = tid >> 5;
    const int qb = blockIdx.x >> 2;
    const int ks = blockIdx.x & 3;
    const int m0 = wid * 16;

    // ---- prologue: Q tile (fp16) via cp.async ----
    {
        const __half* ghq = g_Gh + (qb * 128) * 128;
        for (int i = tid; i < 2048; i += 256) {
            int r = i >> 4, c = i & 15;
            CPA16(sb + SQH + r * QSTR + c * 16, (const char*)(ghq + r * 128 + c * 8));
        }
    }
    // ---- tile 0 K/V ----
    {
        int kbase = ks * 2048;
        unsigned bo = sb + BUF0;
        for (int i = tid; i < 1024; i += 256) {
            int r = i >> 4, c = i & 15;
            CPA16(bo + KH_O + r * QSTR + c * 16, (const char*)(g_Gh + (kbase + r) * 128 + c * 8));
        }
        for (int i = tid; i < 1024; i += 256) {
            int d = i >> 3, c = i & 7;
            CPA16(bo + VH_O + d * VSTR + c * 16, (const char*)(g_Vth + d * NN + kbase + c * 8));
        }
    }
    CP_COMMIT();
    CP_WAIT0();
    __syncthreads();

    const unsigned aoff = (unsigned)(m0 + (lane & 15)) * QSTR + (unsigned)(lane >> 4) * 16;
    const unsigned brow = (unsigned)((lane & 7) + ((lane >> 4) << 3));
    const unsigned bc16 = (unsigned)((lane >> 3) & 1) * 16;
    const unsigned kboff = brow * QSTR + bc16;
    const unsigned vboff = brow * VSTR + bc16;

    float O[16][4];
    #pragma unroll
    for (int j = 0; j < 16; j++)
        #pragma unroll
        for (int i = 0; i < 4; i++) O[j][i] = 0.f;
    float rs_lo = 0.f, rs_hi = 0.f;

    for (int it = 0; it < NITER; it++) {
        unsigned cur = sb + BUF0 + (unsigned)(it & 1) * BUFS;

        // prefetch next tile
        if (it + 1 < NITER) {
            int kbase = ks * 2048 + (it + 1) * 64;
            unsigned bo = sb + BUF0 + (unsigned)((it + 1) & 1) * BUFS;
            for (int i = tid; i < 1024; i += 256) {
                int r = i >> 4, c = i & 15;
                CPA16(bo + KH_O + r * QSTR + c * 16, (const char*)(g_Gh + (kbase + r) * 128 + c * 8));
            }
            for (int i = tid; i < 1024; i += 256) {
                int d = i >> 3, c = i & 7;
                CPA16(bo + VH_O + d * VSTR + c * 16, (const char*)(g_Vth + d * NN + kbase + c * 8));
            }
        }
        CP_COMMIT();

        // ---- S = Q.K^T single fp16 (m16 x n64, k=128) ----
        float S[8][4];
        #pragma unroll
        for (int j = 0; j < 8; j++)
            #pragma unroll
            for (int i = 0; i < 4; i++) S[j][i] = 0.f;

        #pragma unroll
        for (int kk = 0; kk < 8; kk++) {
            unsigned k2 = kk * 32;
            unsigned qf[4];
            LDSM4(qf, sb + SQH + aoff + k2);
            #pragma unroll
            for (int nt = 0; nt < 4; nt++) {
                unsigned kh[4];
                LDSM4(kh, cur + KH_O + (unsigned)(nt * 16) * QSTR + kboff + k2);
                MMA_F16(S[2 * nt],     qf, kh[0], kh[1]);
                MMA_F16(S[2 * nt + 1], qf, kh[2], kh[3]);
            }
        }

        // ---- P = exp(S) packed to bf16; rowsum over the SAME rounded values ----
        unsigned AH[4][4];
        #pragma unroll
        for (int j = 0; j < 8; j++) {
            int c = j >> 1, o = (j & 1) * 2;
            unsigned p01 = pack_bf16x2(__expf(S[j][0]), __expf(S[j][1]));
            unsigned p23 = pack_bf16x2(__expf(S[j][2]), __expf(S[j][3]));
            AH[c][o]     = p01;
            AH[c][o + 1] = p23;
            rs_lo += __uint_as_float(p01 << 16) + __uint_as_float(p01 & 0xffff0000u);
            rs_hi += __uint_as_float(p23 << 16) + __uint_as_float(p23 & 0xffff0000u);
        }

        // ---- O += P.Vhi  (m16 x n128, k=64); Vlo handled as diagonal fix in k_norm ----
        #pragma unroll
        for (int c = 0; c < 4; c++) {
            unsigned k2 = c * 32;
            #pragma unroll
            for (int nt = 0; nt < 8; nt++) {
                unsigned vh[4];
                LDSM4(vh, cur + VH_O + (unsigned)(nt * 16) * VSTR + vboff + k2);
                MMA_BF16(O[2 * nt],     AH[c], vh[0], vh[1]);
                MMA_BF16(O[2 * nt + 1], AH[c], vh[2], vh[3]);
            }
        }

        CP_WAIT0();
        __syncthreads();
    }

    // ---- rowsum reduce within quad, write ----
    rs_lo += __shfl_xor_sync(0xffffffffu, rs_lo, 1);
    rs_lo += __shfl_xor_sync(0xffffffffu, rs_lo, 2);
    rs_hi += __shfl_xor_sync(0xffffffffu, rs_hi, 1);
    rs_hi += __shfl_xor_sync(0xffffffffu, rs_hi, 2);
    int r0 = qb * 128 + m0 + (lane >> 2);
    if ((lane & 3) == 0) {
        atomicAdd(&g_rsum[r0], rs_lo);
        atomicAdd(&g_rsum[r0 + 8], rs_hi);
    }

    // ---- O writeback (split-K atomics) ----
    #pragma unroll
    for (int j = 0; j < 16; j++) {
        int n = 8 * j + 2 * (lane & 3);
        float* b0 = (n < 64) ? &g_accm[r0 * 64 + n] : &g_accp[r0 * 64 + n - 64];
        float* b1 = (n < 64) ? &g_accm[(r0 + 8) * 64 + n] : &g_accp[(r0 + 8) * 64 + n - 64];
        atomicAdd(b0,     O[j][0]);
        atomicAdd(b0 + 1, O[j][1]);
        atomicAdd(b1,     O[j][2]);
        atomicAdd(b1 + 1, O[j][3]);
    }
}

// ---- normalize + diagonal Vlo correction ----
__global__ void k_norm(const float* __restrict__ mag, const float* __restrict__ phase,
                       float* __restrict__ out) {
    int tid = threadIdx.x;             // 256 = 4 rows x 64
    int sub = tid >> 6;
    int d = tid & 63;
    int row = blockIdx.x * 4 + sub;
    float m = mag[row * 64 + d];
    float p = phase[row * 64 + d];

    float pii = g_ediag[row];
    float inv = 1.f / g_rsum[row];
    float vlom = m - __bfloat162float(__float2bfloat16(m));
    float vlop = p - __bfloat162float(__float2bfloat16(p));
    out[row * 64 + d]           = (g_accm[row * 64 + d] + pii * vlom) * inv;
    out[NN * DD + row * 64 + d] = (g_accp[row * 64 + d] + pii * vlop) * inv;
}

extern "C" void kernel_launch(void* const* d_in, const int* in_sizes, int n_in,
                              void* d_out, int out_size) {
    const float* mag   = (const float*)d_in[0];
    const float* phase = (const float*)d_in[1];
    const void*  ei    = d_in[2];
    const float* ea    = (const float*)d_in[3];
    const float* W     = (const float*)d_in[4];
    const float* b     = (const float*)d_in[5];
    float* out = (float*)d_out;

    cudaFuncSetAttribute(k_main, cudaFuncAttributeMaxDynamicSharedMemorySize, SMEMSZ);

    void *p_hash, *p_accm, *p_accp, *p_rsum, *p_ne;
    cudaGetSymbolAddress(&p_hash, g_hash);
    cudaGetSymbolAddress(&p_accm, g_accm);
    cudaGetSymbolAddress(&p_accp, g_accp);
    cudaGetSymbolAddress(&p_rsum, g_rsum);
    cudaGetSymbolAddress(&p_ne,   g_ne);

    k_wsum<<<1, 64>>>(W, b, (const unsigned*)ei);
    k_prep<<<NN / 8, 256>>>(mag, phase);
    dim3 gv(NN / 32, 4);
    k_prepv<<<gv, 256>>>(mag, phase);
    cudaMemsetAsync(p_hash, 0xFF, HSIZE * sizeof(unsigned long long), 0);
    cudaMemsetAsync(p_accm, 0, NN * DD * sizeof(float), 0);
    cudaMemsetAsync(p_accp, 0, NN * DD * sizeof(float), 0);
    cudaMemsetAsync(p_rsum, 0, NN * sizeof(float), 0);
    cudaMemsetAsync(p_ne,   0, sizeof(int), 0);
    k_edge<<<EE / 256, 256>>>(ei, ea);
    k_compact<<<HSIZE / 256, 256>>>();
    k_main<<<ATTN_CTAS + CORR_CTAS, 256, SMEMSZ>>>(mag, phase);
    k_norm<<<NN / 4, 256>>>(mag, phase, out);
}

// round 13
// speedup vs baseline: 1.3830x; 1.3830x over previous
#include <cuda_runtime.h>
#include <cuda_bf16.h>
#include <cuda_fp16.h>
#include <math.h>

#define NN 8192
#define DD 64
#define EE 262144
#define HSIZE (1u << 19)
#define HMASK (HSIZE - 1u)
#define HEMPTY 0xFFFFFFFFFFFFFFFFull

// ===================== base-ISA tensor primitives =====================
#define MMA_BF16(C, A, B0, B1) \
    asm volatile("mma.sync.aligned.m16n8k16.row.col.f32.bf16.bf16.f32 " \
        "{%0,%1,%2,%3}, {%4,%5,%6,%7}, {%8,%9}, {%0,%1,%2,%3};" \
        : "+f"((C)[0]), "+f"((C)[1]), "+f"((C)[2]), "+f"((C)[3]) \
        : "r"((A)[0]), "r"((A)[1]), "r"((A)[2]), "r"((A)[3]), "r"(B0), "r"(B1))

#define MMA_F16(C, A, B0, B1) \
    asm volatile("mma.sync.aligned.m16n8k16.row.col.f32.f16.f16.f32 " \
        "{%0,%1,%2,%3}, {%4,%5,%6,%7}, {%8,%9}, {%0,%1,%2,%3};" \
        : "+f"((C)[0]), "+f"((C)[1]), "+f"((C)[2]), "+f"((C)[3]) \
        : "r"((A)[0]), "r"((A)[1]), "r"((A)[2]), "r"((A)[3]), "r"(B0), "r"(B1))

#define LDSM4(R, addr) \
    asm volatile("ldmatrix.sync.aligned.m8n8.x4.shared.b16 {%0,%1,%2,%3}, [%4];" \
        : "=r"((R)[0]), "=r"((R)[1]), "=r"((R)[2]), "=r"((R)[3]) : "r"(addr))

#define CPA16(dst, src) \
    asm volatile("cp.async.cg.shared.global [%0], [%1], 16;" :: "r"(dst), "l"(src))
#define CP_COMMIT() asm volatile("cp.async.commit_group;" ::: "memory")
#define CP_WAIT0()  asm volatile("cp.async.wait_group 0;" ::: "memory")

__device__ __forceinline__ unsigned pack_bf16x2(float lo, float hi) {
    unsigned r;
    asm("cvt.rn.bf16x2.f32 %0, %1, %2;" : "=r"(r) : "f"(hi), "f"(lo));
    return r;
}

// ===================== static device scratch =====================
__device__ float g_G[NN * 128];                 // fp32 G (corr exact scores)
__device__ __half g_Gh[NN * 128];               // fp16 G (S matmul)
__device__ __nv_bfloat16 g_Vth[128 * NN];       // V^T bf16 (PV matmul)
__device__ float g_ediag[NN];                   // exp(||mag_i||^2)
__device__ float g_rsum[NN];
__device__ float g_accm[NN * DD];
__device__ float g_accp[NN * DD];
__device__ unsigned long long g_hash[HSIZE];
__device__ float g_escore[EE];
__device__ int   g_ne;
__device__ int   g_csrc[EE];
__device__ int   g_cdst[EE];
__device__ float g_cbias[EE];
__device__ float g_wsum4[4];
__device__ float g_bsum;
__device__ int   g_idx64;

// ===================== small kernels =====================
// wsum reduction + edge_index dtype detect (fused)
__global__ void k_wsum(const float* __restrict__ W, const float* __restrict__ b,
                       const unsigned* __restrict__ ei) {
    __shared__ float red[5][64];
    int t = threadIdx.x;
    red[0][t] = W[t * 4 + 0];
    red[1][t] = W[t * 4 + 1];
    red[2][t] = W[t * 4 + 2];
    red[3][t] = W[t * 4 + 3];
    red[4][t] = b[t];
    __syncthreads();
    if (t < 5) {
        float s = 0.f;
        #pragma unroll
        for (int i = 0; i < 64; i++) s += red[t][i];
        if (t < 4) g_wsum4[t] = s;
        else       g_bsum = s;
    }
    if (t == 0) {
        int all0 = 1;
        #pragma unroll
        for (int i = 1; i < 64; i += 2)
            if (ei[i] != 0u) all0 = 0;
        g_idx64 = all0;
    }
}

// G build + ediag (fused, warp per row)
__global__ void k_prep(const float* __restrict__ mag, const float* __restrict__ phase) {
    int w = (blockIdx.x * blockDim.x + threadIdx.x) >> 5;   // row
    int lane = threadIdx.x & 31;
    float2 m  = *(const float2*)(mag + w * 64 + lane * 2);
    float2 ph = *(const float2*)(phase + w * 64 + lane * 2);
    float s0, c0, s1, c1;
    sincosf(ph.x, &s0, &c0);
    sincosf(ph.y, &s1, &c1);
    float gc0 = m.x * c0, gc1 = m.y * c1, gs0 = m.x * s0, gs1 = m.y * s1;
    *(float2*)(g_G + w * 128 + lane * 2)      = make_float2(gc0, gc1);
    *(float2*)(g_G + w * 128 + 64 + lane * 2) = make_float2(gs0, gs1);
    __half2* gh = (__half2*)(g_Gh + w * 128);
    gh[lane]      = __floats2half2_rn(gc0, gc1);
    gh[32 + lane] = __floats2half2_rn(gs0, gs1);
    float s = m.x * m.x + m.y * m.y;
    #pragma unroll
    for (int o = 16; o; o >>= 1) s += __shfl_xor_sync(0xffffffffu, s, o);
    if (lane == 0) g_ediag[w] = __expf(s);
}

// transpose [k][d] -> Vt[d][k] bf16 (32x32 tiles)
__global__ void k_prepv(const float* __restrict__ mag, const float* __restrict__ phase) {
    __shared__ float t[32][33];
    int k0 = blockIdx.x * 32;
    int d0 = blockIdx.y * 32;
    int tx = threadIdx.x & 31, ty = threadIdx.x >> 5;
    const float* src = (d0 < 64) ? mag : phase;
    int dcol = (d0 < 64) ? d0 : d0 - 64;
    #pragma unroll
    for (int r = 0; r < 4; r++) {
        int k = k0 + ty + r * 8;
        t[ty + r * 8][tx] = src[k * 64 + dcol + tx];
    }
    __syncthreads();
    #pragma unroll
    for (int r = 0; r < 4; r++) {
        int d = d0 + ty + r * 8;
        g_Vth[d * NN + k0 + tx] = __float2bfloat16(t[tx][ty + r * 8]);
    }
}

// ---- hash insert helper (last edge index wins via atomicMax on (key|e)) ----
__device__ __forceinline__ void hash_insert(unsigned key, unsigned e) {
    unsigned long long entry = ((unsigned long long)key << 32) | e;
    unsigned h = key * 0x9E3779B1u;
    h ^= h >> 15;
    h &= HMASK;
    for (;;) {
        unsigned long long cur = g_hash[h];
        if (cur == HEMPTY) {
            unsigned long long prev = atomicCAS(&g_hash[h], HEMPTY, entry);
            if (prev == HEMPTY) break;
            cur = prev;
        }
        if ((unsigned)(cur >> 32) == key) {
            atomicMax(&g_hash[h], entry);
            break;
        }
        h = (h + 1) & HMASK;
    }
}

// ---- edge scores + dedupe: 2 edges per thread for MLP on the latency-bound path ----
__global__ void k_edge(const void* __restrict__ eiv, const float* __restrict__ ea) {
    int t = blockIdx.x * blockDim.x + threadIdx.x;
    int e0 = 2 * t, e1 = 2 * t + 1;
    if (e1 >= EE) return;
    int s0, d0, s1, d1;
    if (g_idx64) {
        const longlong2* ei = (const longlong2*)eiv;
        longlong2 a = ei[t];
        longlong2 b = ei[EE / 2 + t];
        s0 = (int)a.x; s1 = (int)a.y;
        d0 = (int)b.x; d1 = (int)b.y;
    } else {
        const int2* ei = (const int2*)eiv;
        int2 a = ei[t];
        int2 b = ei[EE / 2 + t];
        s0 = a.x; s1 = a.y;
        d0 = b.x; d1 = b.y;
    }
    s0 &= 8191; d0 &= 8191; s1 &= 8191; d1 &= 8191;

    float4 a0 = ((const float4*)ea)[e0];
    float4 a1 = ((const float4*)ea)[e1];
    float sc0 = a0.x * g_wsum4[0] + a0.y * g_wsum4[1] + a0.z * g_wsum4[2] + a0.w * g_wsum4[3] + g_bsum;
    float sc1 = a1.x * g_wsum4[0] + a1.y * g_wsum4[1] + a1.z * g_wsum4[2] + a1.w * g_wsum4[3] + g_bsum;
    g_escore[e0] = sc0;
    g_escore[e1] = sc1;

    hash_insert(((unsigned)s0 << 13) | (unsigned)d0, (unsigned)e0);
    hash_insert(((unsigned)s1 << 13) | (unsigned)d1, (unsigned)e1);
}

// ---- compact: 2 hash entries per thread (vectorized scan) ----
__global__ void k_compact() {
    unsigned t = blockIdx.x * blockDim.x + threadIdx.x;
    ulonglong2 pair = ((const ulonglong2*)g_hash)[t];
    #pragma unroll
    for (int i = 0; i < 2; i++) {
        unsigned long long cur = (i == 0) ? pair.x : pair.y;
        if (cur == HEMPTY) continue;
        unsigned key = (unsigned)(cur >> 32);
        unsigned e   = (unsigned)(cur & 0xFFFFFFFFu);
        int pos = atomicAdd(&g_ne, 1);
        g_csrc[pos]  = (int)(key >> 13);
        g_cdst[pos]  = (int)(key & 8191u);
        g_cbias[pos] = g_escore[e];
    }
}

// ===================== mma.sync flash attention (R10 proven config) =====================
// grid=256: qb = bid>>2 (128 q rows), ks = bid&3 (split-K quarter = 2048 keys)
#define QSTR 272
#define VSTR 144
#define SQH  0
#define BUF0 34816
#define BUFS 35840
#define KH_O 0
#define VH_O 17408
#define SMEMSZ (BUF0 + 2 * BUFS)   // 106496
#define NITER 32

__global__ void __launch_bounds__(256, 2)
k_attn() {
    extern __shared__ __align__(1024) char smem[];
    unsigned sb;
    asm("{ .reg .u64 t; cvta.to.shared.u64 t, %1; cvt.u32.u64 %0, t; }"
        : "=r"(sb) : "l"(smem));

    const int tid = threadIdx.x;
    const int lane = tid & 31;
    const int wid = tid >> 5;
    const int qb = blockIdx.x >> 2;
    const int ks = blockIdx.x & 3;
    const int m0 = wid * 16;

    // ---- prologue: Q tile (fp16) via cp.async ----
    {
        const __half* ghq = g_Gh + (qb * 128) * 128;
        for (int i = tid; i < 2048; i += 256) {
            int r = i >> 4, c = i & 15;
            CPA16(sb + SQH + r * QSTR + c * 16, (const char*)(ghq + r * 128 + c * 8));
        }
    }
    // ---- tile 0 K/V ----
    {
        int kbase = ks * 2048;
        unsigned bo = sb + BUF0;
        for (int i = tid; i < 1024; i += 256) {
            int r = i >> 4, c = i & 15;
            CPA16(bo + KH_O + r * QSTR + c * 16, (const char*)(g_Gh + (kbase + r) * 128 + c * 8));
        }
        for (int i = tid; i < 1024; i += 256) {
            int d = i >> 3, c = i & 7;
            CPA16(bo + VH_O + d * VSTR + c * 16, (const char*)(g_Vth + d * NN + kbase + c * 8));
        }
    }
    CP_COMMIT();
    CP_WAIT0();
    __syncthreads();

    const unsigned aoff = (unsigned)(m0 + (lane & 15)) * QSTR + (unsigned)(lane >> 4) * 16;
    const unsigned brow = (unsigned)((lane & 7) + ((lane >> 4) << 3));
    const unsigned bc16 = (unsigned)((lane >> 3) & 1) * 16;
    const unsigned kboff = brow * QSTR + bc16;
    const unsigned vboff = brow * VSTR + bc16;

    float O[16][4];
    #pragma unroll
    for (int j = 0; j < 16; j++)
        #pragma unroll
        for (int i = 0; i < 4; i++) O[j][i] = 0.f;
    float rs_lo = 0.f, rs_hi = 0.f;

    for (int it = 0; it < NITER; it++) {
        unsigned cur = sb + BUF0 + (unsigned)(it & 1) * BUFS;

        // prefetch next tile
        if (it + 1 < NITER) {
            int kbase = ks * 2048 + (it + 1) * 64;
            unsigned bo = sb + BUF0 + (unsigned)((it + 1) & 1) * BUFS;
            for (int i = tid; i < 1024; i += 256) {
                int r = i >> 4, c = i & 15;
                CPA16(bo + KH_O + r * QSTR + c * 16, (const char*)(g_Gh + (kbase + r) * 128 + c * 8));
            }
            for (int i = tid; i < 1024; i += 256) {
                int d = i >> 3, c = i & 7;
                CPA16(bo + VH_O + d * VSTR + c * 16, (const char*)(g_Vth + d * NN + kbase + c * 8));
            }
        }
        CP_COMMIT();

        // ---- S = Q.K^T single fp16 (m16 x n64, k=128) ----
        float S[8][4];
        #pragma unroll
        for (int j = 0; j < 8; j++)
            #pragma unroll
            for (int i = 0; i < 4; i++) S[j][i] = 0.f;

        #pragma unroll
        for (int kk = 0; kk < 8; kk++) {
            unsigned k2 = kk * 32;
            unsigned qf[4];
            LDSM4(qf, sb + SQH + aoff + k2);
            #pragma unroll
            for (int nt = 0; nt < 4; nt++) {
                unsigned kh[4];
                LDSM4(kh, cur + KH_O + (unsigned)(nt * 16) * QSTR + kboff + k2);
                MMA_F16(S[2 * nt],     qf, kh[0], kh[1]);
                MMA_F16(S[2 * nt + 1], qf, kh[2], kh[3]);
            }
        }

        // ---- P = exp(S) packed to bf16; rowsum over the SAME rounded values ----
        unsigned AH[4][4];
        #pragma unroll
        for (int j = 0; j < 8; j++) {
            int c = j >> 1, o = (j & 1) * 2;
            unsigned p01 = pack_bf16x2(__expf(S[j][0]), __expf(S[j][1]));
            unsigned p23 = pack_bf16x2(__expf(S[j][2]), __expf(S[j][3]));
            AH[c][o]     = p01;
            AH[c][o + 1] = p23;
            rs_lo += __uint_as_float(p01 << 16) + __uint_as_float(p01 & 0xffff0000u);
            rs_hi += __uint_as_float(p23 << 16) + __uint_as_float(p23 & 0xffff0000u);
        }

        // ---- O += P.Vhi  (m16 x n128, k=64); Vlo handled as diagonal fix in k_norm ----
        #pragma unroll
        for (int c = 0; c < 4; c++) {
            unsigned k2 = c * 32;
            #pragma unroll
            for (int nt = 0; nt < 8; nt++) {
                unsigned vh[4];
                LDSM4(vh, cur + VH_O + (unsigned)(nt * 16) * VSTR + vboff + k2);
                MMA_BF16(O[2 * nt],     AH[c], vh[0], vh[1]);
                MMA_BF16(O[2 * nt + 1], AH[c], vh[2], vh[3]);
            }
        }

        CP_WAIT0();
        __syncthreads();
    }

    // ---- rowsum reduce within quad, write ----
    rs_lo += __shfl_xor_sync(0xffffffffu, rs_lo, 1);
    rs_lo += __shfl_xor_sync(0xffffffffu, rs_lo, 2);
    rs_hi += __shfl_xor_sync(0xffffffffu, rs_hi, 1);
    rs_hi += __shfl_xor_sync(0xffffffffu, rs_hi, 2);
    int r0 = qb * 128 + m0 + (lane >> 2);
    if ((lane & 3) == 0) {
        atomicAdd(&g_rsum[r0], rs_lo);
        atomicAdd(&g_rsum[r0 + 8], rs_hi);
    }

    // ---- O writeback (split-K atomics) ----
    #pragma unroll
    for (int j = 0; j < 16; j++) {
        int n = 8 * j + 2 * (lane & 3);
        float* b0 = (n < 64) ? &g_accm[r0 * 64 + n] : &g_accp[r0 * 64 + n - 64];
        float* b1 = (n < 64) ? &g_accm[(r0 + 8) * 64 + n] : &g_accp[(r0 + 8) * 64 + n - 64];
        atomicAdd(b0,     O[j][0]);
        atomicAdd(b0 + 1, O[j][1]);
        atomicAdd(b1,     O[j][2]);
        atomicAdd(b1 + 1, O[j][3]);
    }
}

// ---- sparse bias corrections: 2 edges per warp (interleaved for MLP), fp32-exact ----
__global__ void k_corr(const float* __restrict__ mag, const float* __restrict__ phase) {
    int wpair = ((blockIdx.x * blockDim.x + threadIdx.x) >> 5) * 2;
    int lane = threadIdx.x & 31;
    int ne = g_ne;
    if (wpair >= ne) return;
    bool two = (wpair + 1 < ne);

    int src0 = g_csrc[wpair],     dst0 = g_cdst[wpair];
    int src1 = two ? g_csrc[wpair + 1] : src0;
    int dst1 = two ? g_cdst[wpair + 1] : dst0;
    float bias0 = g_cbias[wpair];
    float bias1 = two ? g_cbias[wpair + 1] : 0.f;

    float4 a0 = ((const float4*)(g_G + src0 * 128))[lane];
    float4 q0 = ((const float4*)(g_G + dst0 * 128))[lane];
    float4 a1 = ((const float4*)(g_G + src1 * 128))[lane];
    float4 q1 = ((const float4*)(g_G + dst1 * 128))[lane];
    float s0 = a0.x * q0.x + a0.y * q0.y + a0.z * q0.z + a0.w * q0.w;
    float s1 = a1.x * q1.x + a1.y * q1.y + a1.z * q1.z + a1.w * q1.w;
    #pragma unroll
    for (int off = 16; off; off >>= 1) {
        s0 += __shfl_xor_sync(0xffffffffu, s0, off);
        s1 += __shfl_xor_sync(0xffffffffu, s1, off);
    }

    float delta0 = __expf(s0) * expm1f(bias0);
    float delta1 = __expf(s1) * expm1f(bias1);

    if (fabsf(delta0) > 3e-7f * g_ediag[src0]) {
        if (lane == 0) atomicAdd(&g_rsum[src0], delta0);
        atomicAdd(&g_accm[src0 * 64 + lane],      delta0 * mag[dst0 * 64 + lane]);
        atomicAdd(&g_accm[src0 * 64 + lane + 32], delta0 * mag[dst0 * 64 + lane + 32]);
        atomicAdd(&g_accp[src0 * 64 + lane],      delta0 * phase[dst0 * 64 + lane]);
        atomicAdd(&g_accp[src0 * 64 + lane + 32], delta0 * phase[dst0 * 64 + lane + 32]);
    }
    if (two && fabsf(delta1) > 3e-7f * g_ediag[src1]) {
        if (lane == 0) atomicAdd(&g_rsum[src1], delta1);
        atomicAdd(&g_accm[src1 * 64 + lane],      delta1 * mag[dst1 * 64 + lane]);
        atomicAdd(&g_accm[src1 * 64 + lane + 32], delta1 * mag[dst1 * 64 + lane + 32]);
        atomicAdd(&g_accp[src1 * 64 + lane],      delta1 * phase[dst1 * 64 + lane]);
        atomicAdd(&g_accp[src1 * 64 + lane + 32], delta1 * phase[dst1 * 64 + lane + 32]);
    }
}

// ---- normalize + diagonal Vlo correction ----
__global__ void k_norm(const float* __restrict__ mag, const float* __restrict__ phase,
                       float* __restrict__ out) {
    int tid = threadIdx.x;             // 256 = 4 rows x 64
    int sub = tid >> 6;
    int d = tid & 63;
    int row = blockIdx.x * 4 + sub;
    float m = mag[row * 64 + d];
    float p = phase[row * 64 + d];

    float pii = g_ediag[row];
    float inv = 1.f / g_rsum[row];
    float vlom = m - __bfloat162float(__float2bfloat16(m));
    float vlop = p - __bfloat162float(__float2bfloat16(p));
    out[row * 64 + d]           = (g_accm[row * 64 + d] + pii * vlom) * inv;
    out[NN * DD + row * 64 + d] = (g_accp[row * 64 + d] + pii * vlop) * inv;
}

extern "C" void kernel_launch(void* const* d_in, const int* in_sizes, int n_in,
                              void* d_out, int out_size) {
    const float* mag   = (const float*)d_in[0];
    const float* phase = (const float*)d_in[1];
    const void*  ei    = d_in[2];
    const float* ea    = (const float*)d_in[3];
    const float* W     = (const float*)d_in[4];
    const float* b     = (const float*)d_in[5];
    float* out = (float*)d_out;

    cudaFuncSetAttribute(k_attn, cudaFuncAttributeMaxDynamicSharedMemorySize, SMEMSZ);

    void *p_hash, *p_accm, *p_accp, *p_rsum, *p_ne;
    cudaGetSymbolAddress(&p_hash, g_hash);
    cudaGetSymbolAddress(&p_accm, g_accm);
    cudaGetSymbolAddress(&p_accp, g_accp);
    cudaGetSymbolAddress(&p_rsum, g_rsum);
    cudaGetSymbolAddress(&p_ne,   g_ne);

    k_wsum<<<1, 64>>>(W, b, (const unsigned*)ei);
    k_prep<<<NN / 8, 256>>>(mag, phase);
    dim3 gv(NN / 32, 4);
    k_prepv<<<gv, 256>>>(mag, phase);
    cudaMemsetAsync(p_hash, 0xFF, HSIZE * sizeof(unsigned long long), 0);
    cudaMemsetAsync(p_accm, 0, NN * DD * sizeof(float), 0);
    cudaMemsetAsync(p_accp, 0, NN * DD * sizeof(float), 0);
    cudaMemsetAsync(p_rsum, 0, NN * sizeof(float), 0);
    cudaMemsetAsync(p_ne,   0, sizeof(int), 0);
    k_edge<<<EE / 512, 256>>>(ei, ea);
    k_compact<<<HSIZE / 512, 256>>>();
    k_attn<<<256, 256, SMEMSZ>>>();
    k_corr<<<EE / 16, 256>>>(mag, phase);   // 8 warps/CTA, 2 edges/warp -> covers all EE slots
    k_norm<<<NN / 4, 256>>>(mag, phase, out);
}

// round 14
// speedup vs baseline: 1.6089x; 1.1633x over previous
#include <cuda_runtime.h>
#include <cuda_bf16.h>
#include <cuda_fp16.h>
#include <math.h>

#define NN 8192
#define DD 64
#define EE 262144
#define HSIZE (1u << 19)
#define HMASK (HSIZE - 1u)
#define HEMPTY 0xFFFFFFFFFFFFFFFFull

// ===================== base-ISA tensor primitives =====================
#define MMA_BF16(C, A, B0, B1) \
    asm volatile("mma.sync.aligned.m16n8k16.row.col.f32.bf16.bf16.f32 " \
        "{%0,%1,%2,%3}, {%4,%5,%6,%7}, {%8,%9}, {%0,%1,%2,%3};" \
        : "+f"((C)[0]), "+f"((C)[1]), "+f"((C)[2]), "+f"((C)[3]) \
        : "r"((A)[0]), "r"((A)[1]), "r"((A)[2]), "r"((A)[3]), "r"(B0), "r"(B1))

#define MMA_F16(C, A, B0, B1) \
    asm volatile("mma.sync.aligned.m16n8k16.row.col.f32.f16.f16.f32 " \
        "{%0,%1,%2,%3}, {%4,%5,%6,%7}, {%8,%9}, {%0,%1,%2,%3};" \
        : "+f"((C)[0]), "+f"((C)[1]), "+f"((C)[2]), "+f"((C)[3]) \
        : "r"((A)[0]), "r"((A)[1]), "r"((A)[2]), "r"((A)[3]), "r"(B0), "r"(B1))

#define LDSM4(R, addr) \
    asm volatile("ldmatrix.sync.aligned.m8n8.x4.shared.b16 {%0,%1,%2,%3}, [%4];" \
        : "=r"((R)[0]), "=r"((R)[1]), "=r"((R)[2]), "=r"((R)[3]) : "r"(addr))

#define CPA16(dst, src) \
    asm volatile("cp.async.cg.shared.global [%0], [%1], 16;" :: "r"(dst), "l"(src))
#define CP_COMMIT() asm volatile("cp.async.commit_group;" ::: "memory")
#define CP_WAIT0()  asm volatile("cp.async.wait_group 0;" ::: "memory")

__device__ __forceinline__ unsigned pack_bf16x2(float lo, float hi) {
    unsigned r;
    asm("cvt.rn.bf16x2.f32 %0, %1, %2;" : "=r"(r) : "f"(hi), "f"(lo));
    return r;
}

// ===================== static device scratch =====================
__device__ float g_G[NN * 128];                 // fp32 G (corr exact scores)
__device__ __half g_Gh[NN * 128];               // fp16 G (S matmul)
__device__ __nv_bfloat16 g_Vth[128 * NN];       // V^T bf16 (PV matmul)
__device__ float g_ediag[NN];                   // exp(||mag_i||^2)
__device__ float g_rsum[NN];
__device__ float g_accm[NN * DD];
__device__ float g_accp[NN * DD];
__device__ unsigned long long g_hash[HSIZE];
__device__ float g_escore[EE];
__device__ int   g_ne;
__device__ int   g_csrc[EE];
__device__ int   g_cdst[EE];
__device__ float g_cbias[EE];
__device__ float g_wsum4[4];
__device__ float g_bsum;
__device__ int   g_idx64;

// ===================== small kernels =====================
__global__ void k_wsum(const float* __restrict__ W, const float* __restrict__ b,
                       const unsigned* __restrict__ ei) {
    __shared__ float red[5][64];
    int t = threadIdx.x;
    red[0][t] = W[t * 4 + 0];
    red[1][t] = W[t * 4 + 1];
    red[2][t] = W[t * 4 + 2];
    red[3][t] = W[t * 4 + 3];
    red[4][t] = b[t];
    __syncthreads();
    if (t < 5) {
        float s = 0.f;
        #pragma unroll
        for (int i = 0; i < 64; i++) s += red[t][i];
        if (t < 4) g_wsum4[t] = s;
        else       g_bsum = s;
    }
    if (t == 0) {
        int all0 = 1;
        #pragma unroll
        for (int i = 1; i < 64; i += 2)
            if (ei[i] != 0u) all0 = 0;
        g_idx64 = all0;
    }
}

// G build + ediag (fused, warp per row)
__global__ void k_prep(const float* __restrict__ mag, const float* __restrict__ phase) {
    int w = (blockIdx.x * blockDim.x + threadIdx.x) >> 5;   // row
    int lane = threadIdx.x & 31;
    float2 m  = *(const float2*)(mag + w * 64 + lane * 2);
    float2 ph = *(const float2*)(phase + w * 64 + lane * 2);
    float s0, c0, s1, c1;
    sincosf(ph.x, &s0, &c0);
    sincosf(ph.y, &s1, &c1);
    float gc0 = m.x * c0, gc1 = m.y * c1, gs0 = m.x * s0, gs1 = m.y * s1;
    *(float2*)(g_G + w * 128 + lane * 2)      = make_float2(gc0, gc1);
    *(float2*)(g_G + w * 128 + 64 + lane * 2) = make_float2(gs0, gs1);
    __half2* gh = (__half2*)(g_Gh + w * 128);
    gh[lane]      = __floats2half2_rn(gc0, gc1);
    gh[32 + lane] = __floats2half2_rn(gs0, gs1);
    float s = m.x * m.x + m.y * m.y;
    #pragma unroll
    for (int o = 16; o; o >>= 1) s += __shfl_xor_sync(0xffffffffu, s, o);
    if (lane == 0) g_ediag[w] = __expf(s);
}

// transpose [k][d] -> Vt[d][k] bf16 (32x32 tiles)
__global__ void k_prepv(const float* __restrict__ mag, const float* __restrict__ phase) {
    __shared__ float t[32][33];
    int k0 = blockIdx.x * 32;
    int d0 = blockIdx.y * 32;
    int tx = threadIdx.x & 31, ty = threadIdx.x >> 5;
    const float* src = (d0 < 64) ? mag : phase;
    int dcol = (d0 < 64) ? d0 : d0 - 64;
    #pragma unroll
    for (int r = 0; r < 4; r++) {
        int k = k0 + ty + r * 8;
        t[ty + r * 8][tx] = src[k * 64 + dcol + tx];
    }
    __syncthreads();
    #pragma unroll
    for (int r = 0; r < 4; r++) {
        int d = d0 + ty + r * 8;
        g_Vth[d * NN + k0 + tx] = __float2bfloat16(t[tx][ty + r * 8]);
    }
}

// ---- edge scores + lock-free dedupe (1 edge/thread: max warps for latency hiding) ----
__global__ void k_edge(const void* __restrict__ eiv, const float* __restrict__ ea) {
    int e = blockIdx.x * blockDim.x + threadIdx.x;
    if (e >= EE) return;
    int src, dst;
    if (g_idx64) {
        const long long* ei = (const long long*)eiv;
        src = (int)ei[e];
        dst = (int)ei[EE + e];
    } else {
        const int* ei = (const int*)eiv;
        src = ei[e];
        dst = ei[EE + e];
    }
    src &= 8191; dst &= 8191;

    float4 a = ((const float4*)ea)[e];
    float score = a.x * g_wsum4[0] + a.y * g_wsum4[1] + a.z * g_wsum4[2] + a.w * g_wsum4[3] + g_bsum;
    g_escore[e] = score;

    unsigned key = ((unsigned)src << 13) | (unsigned)dst;
    unsigned long long entry = ((unsigned long long)key << 32) | (unsigned)e;
    unsigned h = key * 0x9E3779B1u;
    h ^= h >> 15;
    h &= HMASK;
    for (;;) {
        unsigned long long cur = g_hash[h];
        if (cur == HEMPTY) {
            unsigned long long prev = atomicCAS(&g_hash[h], HEMPTY, entry);
            if (prev == HEMPTY) break;
            cur = prev;
        }
        if ((unsigned)(cur >> 32) == key) {
            atomicMax(&g_hash[h], entry);
            break;
        }
        h = (h + 1) & HMASK;
    }
}

// ---- compact: 2 hash entries per thread (memory-bound scan, vectorization is free) ----
__global__ void k_compact() {
    unsigned t = blockIdx.x * blockDim.x + threadIdx.x;
    ulonglong2 pair = ((const ulonglong2*)g_hash)[t];
    #pragma unroll
    for (int i = 0; i < 2; i++) {
        unsigned long long cur = (i == 0) ? pair.x : pair.y;
        if (cur == HEMPTY) continue;
        unsigned key = (unsigned)(cur >> 32);
        unsigned e   = (unsigned)(cur & 0xFFFFFFFFu);
        int pos = atomicAdd(&g_ne, 1);
        g_csrc[pos]  = (int)(key >> 13);
        g_cdst[pos]  = (int)(key & 8191u);
        g_cbias[pos] = g_escore[e];
    }
}

// ===================== mma.sync flash attention (R10 proven config) =====================
#define QSTR 272
#define VSTR 144
#define SQH  0
#define BUF0 34816
#define BUFS 35840
#define KH_O 0
#define VH_O 17408
#define SMEMSZ (BUF0 + 2 * BUFS)   // 106496
#define NITER 32

__global__ void __launch_bounds__(256, 2)
k_attn() {
    extern __shared__ __align__(1024) char smem[];
    unsigned sb;
    asm("{ .reg .u64 t; cvta.to.shared.u64 t, %1; cvt.u32.u64 %0, t; }"
        : "=r"(sb) : "l"(smem));

    const int tid = threadIdx.x;
    const int lane = tid & 31;
    const int wid = tid >> 5;
    const int qb = blockIdx.x >> 2;
    const int ks = blockIdx.x & 3;
    const int m0 = wid * 16;

    {
        const __half* ghq = g_Gh + (qb * 128) * 128;
        for (int i = tid; i < 2048; i += 256) {
            int r = i >> 4, c = i & 15;
            CPA16(sb + SQH + r * QSTR + c * 16, (const char*)(ghq + r * 128 + c * 8));
        }
    }
    {
        int kbase = ks * 2048;
        unsigned bo = sb + BUF0;
        for (int i = tid; i < 1024; i += 256) {
            int r = i >> 4, c = i & 15;
            CPA16(bo + KH_O + r * QSTR + c * 16, (const char*)(g_Gh + (kbase + r) * 128 + c * 8));
        }
        for (int i = tid; i < 1024; i += 256) {
            int d = i >> 3, c = i & 7;
            CPA16(bo + VH_O + d * VSTR + c * 16, (const char*)(g_Vth + d * NN + kbase + c * 8));
        }
    }
    CP_COMMIT();
    CP_WAIT0();
    __syncthreads();

    const unsigned aoff = (unsigned)(m0 + (lane & 15)) * QSTR + (unsigned)(lane >> 4) * 16;
    const unsigned brow = (unsigned)((lane & 7) + ((lane >> 4) << 3));
    const unsigned bc16 = (unsigned)((lane >> 3) & 1) * 16;
    const unsigned kboff = brow * QSTR + bc16;
    const unsigned vboff = brow * VSTR + bc16;

    float O[16][4];
    #pragma unroll
    for (int j = 0; j < 16; j++)
        #pragma unroll
        for (int i = 0; i < 4; i++) O[j][i] = 0.f;
    float rs_lo = 0.f, rs_hi = 0.f;

    for (int it = 0; it < NITER; it++) {
        unsigned cur = sb + BUF0 + (unsigned)(it & 1) * BUFS;

        if (it + 1 < NITER) {
            int kbase = ks * 2048 + (it + 1) * 64;
            unsigned bo = sb + BUF0 + (unsigned)((it + 1) & 1) * BUFS;
            for (int i = tid; i < 1024; i += 256) {
                int r = i >> 4, c = i & 15;
                CPA16(bo + KH_O + r * QSTR + c * 16, (const char*)(g_Gh + (kbase + r) * 128 + c * 8));
            }
            for (int i = tid; i < 1024; i += 256) {
                int d = i >> 3, c = i & 7;
                CPA16(bo + VH_O + d * VSTR + c * 16, (const char*)(g_Vth + d * NN + kbase + c * 8));
            }
        }
        CP_COMMIT();

        float S[8][4];
        #pragma unroll
        for (int j = 0; j < 8; j++)
            #pragma unroll
            for (int i = 0; i < 4; i++) S[j][i] = 0.f;

        #pragma unroll
        for (int kk = 0; kk < 8; kk++) {
            unsigned k2 = kk * 32;
            unsigned qf[4];
            LDSM4(qf, sb + SQH + aoff + k2);
            #pragma unroll
            for (int nt = 0; nt < 4; nt++) {
                unsigned kh[4];
                LDSM4(kh, cur + KH_O + (unsigned)(nt * 16) * QSTR + kboff + k2);
                MMA_F16(S[2 * nt],     qf, kh[0], kh[1]);
                MMA_F16(S[2 * nt + 1], qf, kh[2], kh[3]);
            }
        }

        unsigned AH[4][4];
        #pragma unroll
        for (int j = 0; j < 8; j++) {
            int c = j >> 1, o = (j & 1) * 2;
            unsigned p01 = pack_bf16x2(__expf(S[j][0]), __expf(S[j][1]));
            unsigned p23 = pack_bf16x2(__expf(S[j][2]), __expf(S[j][3]));
            AH[c][o]     = p01;
            AH[c][o + 1] = p23;
            rs_lo += __uint_as_float(p01 << 16) + __uint_as_float(p01 & 0xffff0000u);
            rs_hi += __uint_as_float(p23 << 16) + __uint_as_float(p23 & 0xffff0000u);
        }

        #pragma unroll
        for (int c = 0; c < 4; c++) {
            unsigned k2 = c * 32;
            #pragma unroll
            for (int nt = 0; nt < 8; nt++) {
                unsigned vh[4];
                LDSM4(vh, cur + VH_O + (unsigned)(nt * 16) * VSTR + vboff + k2);
                MMA_BF16(O[2 * nt],     AH[c], vh[0], vh[1]);
                MMA_BF16(O[2 * nt + 1], AH[c], vh[2], vh[3]);
            }
        }

        CP_WAIT0();
        __syncthreads();
    }

    rs_lo += __shfl_xor_sync(0xffffffffu, rs_lo, 1);
    rs_lo += __shfl_xor_sync(0xffffffffu, rs_lo, 2);
    rs_hi += __shfl_xor_sync(0xffffffffu, rs_hi, 1);
    rs_hi += __shfl_xor_sync(0xffffffffu, rs_hi, 2);
    int r0 = qb * 128 + m0 + (lane >> 2);
    if ((lane & 3) == 0) {
        atomicAdd(&g_rsum[r0], rs_lo);
        atomicAdd(&g_rsum[r0 + 8], rs_hi);
    }

    #pragma unroll
    for (int j = 0; j < 16; j++) {
        int n = 8 * j + 2 * (lane & 3);
        float* b0 = (n < 64) ? &g_accm[r0 * 64 + n] : &g_accp[r0 * 64 + n - 64];
        float* b1 = (n < 64) ? &g_accm[(r0 + 8) * 64 + n] : &g_accp[(r0 + 8) * 64 + n - 64];
        atomicAdd(b0,     O[j][0]);
        atomicAdd(b0 + 1, O[j][1]);
        atomicAdd(b1,     O[j][2]);
        atomicAdd(b1 + 1, O[j][3]);
    }
}

// ---- sparse bias corrections: 1 edge/warp (max warp count), fp32-exact, threshold skip ----
__global__ void k_corr(const float* __restrict__ mag, const float* __restrict__ phase) {
    int w = (blockIdx.x * blockDim.x + threadIdx.x) >> 5;
    int lane = threadIdx.x & 31;
    if (w >= g_ne) return;
    int src = g_csrc[w], dst = g_cdst[w];
    float bias = g_cbias[w];

    const float4* Gs = (const float4*)(g_G + src * 128);
    const float4* Gd = (const float4*)(g_G + dst * 128);
    float4 a = Gs[lane], q = Gd[lane];
    float s = a.x * q.x + a.y * q.y + a.z * q.z + a.w * q.w;
    #pragma unroll
    for (int off = 16; off; off >>= 1) s += __shfl_xor_sync(0xffffffffu, s, off);

    float delta = __expf(s) * expm1f(bias);
    if (fabsf(delta) <= 3e-7f * g_ediag[src]) return;   // uniform across warp

    if (lane == 0) atomicAdd(&g_rsum[src], delta);
    atomicAdd(&g_accm[src * 64 + lane],      delta * mag[dst * 64 + lane]);
    atomicAdd(&g_accm[src * 64 + lane + 32], delta * mag[dst * 64 + lane + 32]);
    atomicAdd(&g_accp[src * 64 + lane],      delta * phase[dst * 64 + lane]);
    atomicAdd(&g_accp[src * 64 + lane + 32], delta * phase[dst * 64 + lane + 32]);
}

// ---- normalize + diagonal Vlo correction ----
__global__ void k_norm(const float* __restrict__ mag, const float* __restrict__ phase,
                       float* __restrict__ out) {
    int tid = threadIdx.x;             // 256 = 4 rows x 64
    int sub = tid >> 6;
    int d = tid & 63;
    int row = blockIdx.x * 4 + sub;
    float m = mag[row * 64 + d];
    float p = phase[row * 64 + d];

    float pii = g_ediag[row];
    float inv = 1.f / g_rsum[row];
    float vlom = m - __bfloat162float(__float2bfloat16(m));
    float vlop = p - __bfloat162float(__float2bfloat16(p));
    out[row * 64 + d]           = (g_accm[row * 64 + d] + pii * vlom) * inv;
    out[NN * DD + row * 64 + d] = (g_accp[row * 64 + d] + pii * vlop) * inv;
}

extern "C" void kernel_launch(void* const* d_in, const int* in_sizes, int n_in,
                              void* d_out, int out_size) {
    const float* mag   = (const float*)d_in[0];
    const float* phase = (const float*)d_in[1];
    const void*  ei    = d_in[2];
    const float* ea    = (const float*)d_in[3];
    const float* W     = (const float*)d_in[4];
    const float* b     = (const float*)d_in[5];
    float* out = (float*)d_out;

    // lazily-created side stream + fork/join events (first call = correctness run,
    // not captured; subsequent capture reuses them — no per-call work difference)
    static cudaStream_t s2 = nullptr;
    static cudaEvent_t eFork = nullptr, eJoin = nullptr;
    if (!s2) {
        cudaStreamCreateWithFlags(&s2, cudaStreamNonBlocking);
        cudaEventCreateWithFlags(&eFork, cudaEventDisableTiming);
        cudaEventCreateWithFlags(&eJoin, cudaEventDisableTiming);
    }

    cudaFuncSetAttribute(k_attn, cudaFuncAttributeMaxDynamicSharedMemorySize, SMEMSZ);

    void *p_hash, *p_accm, *p_accp, *p_rsum, *p_ne;
    cudaGetSymbolAddress(&p_hash, g_hash);
    cudaGetSymbolAddress(&p_accm, g_accm);
    cudaGetSymbolAddress(&p_accp, g_accp);
    cudaGetSymbolAddress(&p_rsum, g_rsum);
    cudaGetSymbolAddress(&p_ne,   g_ne);

    // ---- serial prologue on main stream ----
    k_wsum<<<1, 64>>>(W, b, (const unsigned*)ei);
    k_prep<<<NN / 8, 256>>>(mag, phase);
    dim3 gv(NN / 32, 4);
    k_prepv<<<gv, 256>>>(mag, phase);
    cudaMemsetAsync(p_hash, 0xFF, HSIZE * sizeof(unsigned long long), 0);
    cudaMemsetAsync(p_accm, 0, NN * DD * sizeof(float), 0);
    cudaMemsetAsync(p_accp, 0, NN * DD * sizeof(float), 0);
    cudaMemsetAsync(p_rsum, 0, NN * sizeof(float), 0);
    cudaMemsetAsync(p_ne,   0, sizeof(int), 0);

    // ---- fork: edge chain on s2 overlaps k_attn on main stream ----
    cudaEventRecord(eFork, 0);
    cudaStreamWaitEvent(s2, eFork, 0);

    k_edge<<<EE / 256, 256, 0, s2>>>(ei, ea);
    k_compact<<<HSIZE / 512, 256, 0, s2>>>();
    k_corr<<<EE / 8, 256, 0, s2>>>(mag, phase);
    cudaEventRecord(eJoin, s2);

    k_attn<<<256, 256, SMEMSZ>>>();

    // ---- join, then normalize ----
    cudaStreamWaitEvent(0, eJoin, 0);
    k_norm<<<NN / 4, 256>>>(mag, phase, out);
}

// round 15
// speedup vs baseline: 1.7555x; 1.0911x over previous
#include <cuda_runtime.h>
#include <cuda_bf16.h>
#include <cuda_fp16.h>
#include <math.h>

#define NN 8192
#define DD 64
#define EE 262144
#define HSIZE (1u << 19)
#define HMASK (HSIZE - 1u)
#define HEMPTY 0xFFFFFFFFFFFFFFFFull

// ===================== base-ISA tensor primitives =====================
#define MMA_BF16(C, A, B0, B1) \
    asm volatile("mma.sync.aligned.m16n8k16.row.col.f32.bf16.bf16.f32 " \
        "{%0,%1,%2,%3}, {%4,%5,%6,%7}, {%8,%9}, {%0,%1,%2,%3};" \
        : "+f"((C)[0]), "+f"((C)[1]), "+f"((C)[2]), "+f"((C)[3]) \
        : "r"((A)[0]), "r"((A)[1]), "r"((A)[2]), "r"((A)[3]), "r"(B0), "r"(B1))

#define MMA_F16(C, A, B0, B1) \
    asm volatile("mma.sync.aligned.m16n8k16.row.col.f32.f16.f16.f32 " \
        "{%0,%1,%2,%3}, {%4,%5,%6,%7}, {%8,%9}, {%0,%1,%2,%3};" \
        : "+f"((C)[0]), "+f"((C)[1]), "+f"((C)[2]), "+f"((C)[3]) \
        : "r"((A)[0]), "r"((A)[1]), "r"((A)[2]), "r"((A)[3]), "r"(B0), "r"(B1))

#define LDSM4(R, addr) \
    asm volatile("ldmatrix.sync.aligned.m8n8.x4.shared.b16 {%0,%1,%2,%3}, [%4];" \
        : "=r"((R)[0]), "=r"((R)[1]), "=r"((R)[2]), "=r"((R)[3]) : "r"(addr))

#define CPA16(dst, src) \
    asm volatile("cp.async.cg.shared.global [%0], [%1], 16;" :: "r"(dst), "l"(src))
#define CP_COMMIT() asm volatile("cp.async.commit_group;" ::: "memory")
#define CP_WAIT0()  asm volatile("cp.async.wait_group 0;" ::: "memory")

__device__ __forceinline__ unsigned pack_bf16x2(float lo, float hi) {
    unsigned r;
    asm("cvt.rn.bf16x2.f32 %0, %1, %2;" : "=r"(r) : "f"(hi), "f"(lo));
    return r;
}

// ===================== static device scratch =====================
__device__ float g_G[NN * 128];                 // fp32 G (corr exact scores)
__device__ __half g_Gh[NN * 128];               // fp16 G (S matmul)
__device__ __nv_bfloat16 g_Vth[128 * NN];       // V^T bf16 (PV matmul)
__device__ float g_ediag[NN];                   // exp(||mag_i||^2)
__device__ float g_rsum[NN];
__device__ float g_accm[NN * DD];
__device__ float g_accp[NN * DD];
__device__ unsigned long long g_hash[HSIZE];
__device__ float g_escore[EE];
__device__ int   g_ne;
__device__ int   g_csrc[EE];
__device__ int   g_cdst[EE];
__device__ float g_cbias[EE];
__device__ float g_wsum4[4];
__device__ float g_bsum;
__device__ int   g_idx64;

// ===================== small kernels =====================
__global__ void k_wsum(const float* __restrict__ W, const float* __restrict__ b,
                       const unsigned* __restrict__ ei) {
    __shared__ float red[5][64];
    int t = threadIdx.x;
    red[0][t] = W[t * 4 + 0];
    red[1][t] = W[t * 4 + 1];
    red[2][t] = W[t * 4 + 2];
    red[3][t] = W[t * 4 + 3];
    red[4][t] = b[t];
    __syncthreads();
    if (t < 5) {
        float s = 0.f;
        #pragma unroll
        for (int i = 0; i < 64; i++) s += red[t][i];
        if (t < 4) g_wsum4[t] = s;
        else       g_bsum = s;
    }
    if (t == 0) {
        int all0 = 1;
        #pragma unroll
        for (int i = 1; i < 64; i += 2)
            if (ei[i] != 0u) all0 = 0;
        g_idx64 = all0;
    }
}

// G build + ediag (fused, warp per row)
__global__ void k_prep(const float* __restrict__ mag, const float* __restrict__ phase) {
    int w = (blockIdx.x * blockDim.x + threadIdx.x) >> 5;   // row
    int lane = threadIdx.x & 31;
    float2 m  = *(const float2*)(mag + w * 64 + lane * 2);
    float2 ph = *(const float2*)(phase + w * 64 + lane * 2);
    float s0, c0, s1, c1;
    sincosf(ph.x, &s0, &c0);
    sincosf(ph.y, &s1, &c1);
    float gc0 = m.x * c0, gc1 = m.y * c1, gs0 = m.x * s0, gs1 = m.y * s1;
    *(float2*)(g_G + w * 128 + lane * 2)      = make_float2(gc0, gc1);
    *(float2*)(g_G + w * 128 + 64 + lane * 2) = make_float2(gs0, gs1);
    __half2* gh = (__half2*)(g_Gh + w * 128);
    gh[lane]      = __floats2half2_rn(gc0, gc1);
    gh[32 + lane] = __floats2half2_rn(gs0, gs1);
    float s = m.x * m.x + m.y * m.y;
    #pragma unroll
    for (int o = 16; o; o >>= 1) s += __shfl_xor_sync(0xffffffffu, s, o);
    if (lane == 0) g_ediag[w] = __expf(s);
}

// transpose [k][d] -> Vt[d][k] bf16 (32x32 tiles)
__global__ void k_prepv(const float* __restrict__ mag, const float* __restrict__ phase) {
    __shared__ float t[32][33];
    int k0 = blockIdx.x * 32;
    int d0 = blockIdx.y * 32;
    int tx = threadIdx.x & 31, ty = threadIdx.x >> 5;
    const float* src = (d0 < 64) ? mag : phase;
    int dcol = (d0 < 64) ? d0 : d0 - 64;
    #pragma unroll
    for (int r = 0; r < 4; r++) {
        int k = k0 + ty + r * 8;
        t[ty + r * 8][tx] = src[k * 64 + dcol + tx];
    }
    __syncthreads();
    #pragma unroll
    for (int r = 0; r < 4; r++) {
        int d = d0 + ty + r * 8;
        g_Vth[d * NN + k0 + tx] = __float2bfloat16(t[tx][ty + r * 8]);
    }
}

// ---- edge scores + lock-free dedupe (1 edge/thread: max warps for latency hiding) ----
__global__ void k_edge(const void* __restrict__ eiv, const float* __restrict__ ea) {
    int e = blockIdx.x * blockDim.x + threadIdx.x;
    if (e >= EE) return;
    int src, dst;
    if (g_idx64) {
        const long long* ei = (const long long*)eiv;
        src = (int)ei[e];
        dst = (int)ei[EE + e];
    } else {
        const int* ei = (const int*)eiv;
        src = ei[e];
        dst = ei[EE + e];
    }
    src &= 8191; dst &= 8191;

    float4 a = ((const float4*)ea)[e];
    float score = a.x * g_wsum4[0] + a.y * g_wsum4[1] + a.z * g_wsum4[2] + a.w * g_wsum4[3] + g_bsum;
    g_escore[e] = score;

    unsigned key = ((unsigned)src << 13) | (unsigned)dst;
    unsigned long long entry = ((unsigned long long)key << 32) | (unsigned)e;
    unsigned h = key * 0x9E3779B1u;
    h ^= h >> 15;
    h &= HMASK;
    for (;;) {
        unsigned long long cur = g_hash[h];
        if (cur == HEMPTY) {
            unsigned long long prev = atomicCAS(&g_hash[h], HEMPTY, entry);
            if (prev == HEMPTY) break;
            cur = prev;
        }
        if ((unsigned)(cur >> 32) == key) {
            atomicMax(&g_hash[h], entry);
            break;
        }
        h = (h + 1) & HMASK;
    }
}

// ---- compact: 2 hash entries per thread (memory-bound scan) ----
__global__ void k_compact() {
    unsigned t = blockIdx.x * blockDim.x + threadIdx.x;
    ulonglong2 pair = ((const ulonglong2*)g_hash)[t];
    #pragma unroll
    for (int i = 0; i < 2; i++) {
        unsigned long long cur = (i == 0) ? pair.x : pair.y;
        if (cur == HEMPTY) continue;
        unsigned key = (unsigned)(cur >> 32);
        unsigned e   = (unsigned)(cur & 0xFFFFFFFFu);
        int pos = atomicAdd(&g_ne, 1);
        g_csrc[pos]  = (int)(key >> 13);
        g_cdst[pos]  = (int)(key & 8191u);
        g_cbias[pos] = g_escore[e];
    }
}

// ===================== mma.sync flash attention (R10 proven config) =====================
#define QSTR 272
#define VSTR 144
#define SQH  0
#define BUF0 34816
#define BUFS 35840
#define KH_O 0
#define VH_O 17408
#define SMEMSZ (BUF0 + 2 * BUFS)   // 106496
#define NITER 32

__global__ void __launch_bounds__(256, 2)
k_attn() {
    extern __shared__ __align__(1024) char smem[];
    unsigned sb;
    asm("{ .reg .u64 t; cvta.to.shared.u64 t, %1; cvt.u32.u64 %0, t; }"
        : "=r"(sb) : "l"(smem));

    const int tid = threadIdx.x;
    const int lane = tid & 31;
    const int wid = tid >> 5;
    const int qb = blockIdx.x >> 2;
    const int ks = blockIdx.x & 3;
    const int m0 = wid * 16;

    {
        const __half* ghq = g_Gh + (qb * 128) * 128;
        for (int i = tid; i < 2048; i += 256) {
            int r = i >> 4, c = i & 15;
            CPA16(sb + SQH + r * QSTR + c * 16, (const char*)(ghq + r * 128 + c * 8));
        }
    }
    {
        int kbase = ks * 2048;
        unsigned bo = sb + BUF0;
        for (int i = tid; i < 1024; i += 256) {
            int r = i >> 4, c = i & 15;
            CPA16(bo + KH_O + r * QSTR + c * 16, (const char*)(g_Gh + (kbase + r) * 128 + c * 8));
        }
        for (int i = tid; i < 1024; i += 256) {
            int d = i >> 3, c = i & 7;
            CPA16(bo + VH_O + d * VSTR + c * 16, (const char*)(g_Vth + d * NN + kbase + c * 8));
        }
    }
    CP_COMMIT();
    CP_WAIT0();
    __syncthreads();

    const unsigned aoff = (unsigned)(m0 + (lane & 15)) * QSTR + (unsigned)(lane >> 4) * 16;
    const unsigned brow = (unsigned)((lane & 7) + ((lane >> 4) << 3));
    const unsigned bc16 = (unsigned)((lane >> 3) & 1) * 16;
    const unsigned kboff = brow * QSTR + bc16;
    const unsigned vboff = brow * VSTR + bc16;

    float O[16][4];
    #pragma unroll
    for (int j = 0; j < 16; j++)
        #pragma unroll
        for (int i = 0; i < 4; i++) O[j][i] = 0.f;
    float rs_lo = 0.f, rs_hi = 0.f;

    for (int it = 0; it < NITER; it++) {
        unsigned cur = sb + BUF0 + (unsigned)(it & 1) * BUFS;

        if (it + 1 < NITER) {
            int kbase = ks * 2048 + (it + 1) * 64;
            unsigned bo = sb + BUF0 + (unsigned)((it + 1) & 1) * BUFS;
            for (int i = tid; i < 1024; i += 256) {
                int r = i >> 4, c = i & 15;
                CPA16(bo + KH_O + r * QSTR + c * 16, (const char*)(g_Gh + (kbase + r) * 128 + c * 8));
            }
            for (int i = tid; i < 1024; i += 256) {
                int d = i >> 3, c = i & 7;
                CPA16(bo + VH_O + d * VSTR + c * 16, (const char*)(g_Vth + d * NN + kbase + c * 8));
            }
        }
        CP_COMMIT();

        float S[8][4];
        #pragma unroll
        for (int j = 0; j < 8; j++)
            #pragma unroll
            for (int i = 0; i < 4; i++) S[j][i] = 0.f;

        #pragma unroll
        for (int kk = 0; kk < 8; kk++) {
            unsigned k2 = kk * 32;
            unsigned qf[4];
            LDSM4(qf, sb + SQH + aoff + k2);
            #pragma unroll
            for (int nt = 0; nt < 4; nt++) {
                unsigned kh[4];
                LDSM4(kh, cur + KH_O + (unsigned)(nt * 16) * QSTR + kboff + k2);
                MMA_F16(S[2 * nt],     qf, kh[0], kh[1]);
                MMA_F16(S[2 * nt + 1], qf, kh[2], kh[3]);
            }
        }

        unsigned AH[4][4];
        #pragma unroll
        for (int j = 0; j < 8; j++) {
            int c = j >> 1, o = (j & 1) * 2;
            unsigned p01 = pack_bf16x2(__expf(S[j][0]), __expf(S[j][1]));
            unsigned p23 = pack_bf16x2(__expf(S[j][2]), __expf(S[j][3]));
            AH[c][o]     = p01;
            AH[c][o + 1] = p23;
            rs_lo += __uint_as_float(p01 << 16) + __uint_as_float(p01 & 0xffff0000u);
            rs_hi += __uint_as_float(p23 << 16) + __uint_as_float(p23 & 0xffff0000u);
        }

        #pragma unroll
        for (int c = 0; c < 4; c++) {
            unsigned k2 = c * 32;
            #pragma unroll
            for (int nt = 0; nt < 8; nt++) {
                unsigned vh[4];
                LDSM4(vh, cur + VH_O + (unsigned)(nt * 16) * VSTR + vboff + k2);
                MMA_BF16(O[2 * nt],     AH[c], vh[0], vh[1]);
                MMA_BF16(O[2 * nt + 1], AH[c], vh[2], vh[3]);
            }
        }

        CP_WAIT0();
        __syncthreads();
    }

    rs_lo += __shfl_xor_sync(0xffffffffu, rs_lo, 1);
    rs_lo += __shfl_xor_sync(0xffffffffu, rs_lo, 2);
    rs_hi += __shfl_xor_sync(0xffffffffu, rs_hi, 1);
    rs_hi += __shfl_xor_sync(0xffffffffu, rs_hi, 2);
    int r0 = qb * 128 + m0 + (lane >> 2);
    if ((lane & 3) == 0) {
        atomicAdd(&g_rsum[r0], rs_lo);
        atomicAdd(&g_rsum[r0 + 8], rs_hi);
    }

    #pragma unroll
    for (int j = 0; j < 16; j++) {
        int n = 8 * j + 2 * (lane & 3);
        float* b0 = (n < 64) ? &g_accm[r0 * 64 + n] : &g_accp[r0 * 64 + n - 64];
        float* b1 = (n < 64) ? &g_accm[(r0 + 8) * 64 + n] : &g_accp[(r0 + 8) * 64 + n - 64];
        atomicAdd(b0,     O[j][0]);
        atomicAdd(b0 + 1, O[j][1]);
        atomicAdd(b1,     O[j][2]);
        atomicAdd(b1 + 1, O[j][3]);
    }
}

// ---- sparse bias corrections: 1 edge/warp, fp32-exact, threshold skip ----
__global__ void k_corr(const float* __restrict__ mag, const float* __restrict__ phase) {
    int w = (blockIdx.x * blockDim.x + threadIdx.x) >> 5;
    int lane = threadIdx.x & 31;
    if (w >= g_ne) return;
    int src = g_csrc[w], dst = g_cdst[w];
    float bias = g_cbias[w];

    const float4* Gs = (const float4*)(g_G + src * 128);
    const float4* Gd = (const float4*)(g_G + dst * 128);
    float4 a = Gs[lane], q = Gd[lane];
    float s = a.x * q.x + a.y * q.y + a.z * q.z + a.w * q.w;
    #pragma unroll
    for (int off = 16; off; off >>= 1) s += __shfl_xor_sync(0xffffffffu, s, off);

    float delta = __expf(s) * expm1f(bias);
    if (fabsf(delta) <= 3e-7f * g_ediag[src]) return;   // uniform across warp

    if (lane == 0) atomicAdd(&g_rsum[src], delta);
    atomicAdd(&g_accm[src * 64 + lane],      delta * mag[dst * 64 + lane]);
    atomicAdd(&g_accm[src * 64 + lane + 32], delta * mag[dst * 64 + lane + 32]);
    atomicAdd(&g_accp[src * 64 + lane],      delta * phase[dst * 64 + lane]);
    atomicAdd(&g_accp[src * 64 + lane + 32], delta * phase[dst * 64 + lane + 32]);
}

// ---- normalize + diagonal Vlo correction ----
__global__ void k_norm(const float* __restrict__ mag, const float* __restrict__ phase,
                       float* __restrict__ out) {
    int tid = threadIdx.x;             // 256 = 4 rows x 64
    int sub = tid >> 6;
    int d = tid & 63;
    int row = blockIdx.x * 4 + sub;
    float m = mag[row * 64 + d];
    float p = phase[row * 64 + d];

    float pii = g_ediag[row];
    float inv = 1.f / g_rsum[row];
    float vlom = m - __bfloat162float(__float2bfloat16(m));
    float vlop = p - __bfloat162float(__float2bfloat16(p));
    out[row * 64 + d]           = (g_accm[row * 64 + d] + pii * vlom) * inv;
    out[NN * DD + row * 64 + d] = (g_accp[row * 64 + d] + pii * vlop) * inv;
}

extern "C" void kernel_launch(void* const* d_in, const int* in_sizes, int n_in,
                              void* d_out, int out_size) {
    const float* mag   = (const float*)d_in[0];
    const float* phase = (const float*)d_in[1];
    const void*  ei    = d_in[2];
    const float* ea    = (const float*)d_in[3];
    const float* W     = (const float*)d_in[4];
    const float* b     = (const float*)d_in[5];
    float* out = (float*)d_out;

    // lazily-created side streams + events (created on uncaptured correctness call,
    // reused during graph capture)
    static cudaStream_t s2 = nullptr, s3 = nullptr;
    static cudaEvent_t eZ = nullptr, eV = nullptr, ePrep = nullptr, eJoin = nullptr, eFork = nullptr;
    if (!s2) {
        cudaStreamCreateWithFlags(&s2, cudaStreamNonBlocking);
        cudaStreamCreateWithFlags(&s3, cudaStreamNonBlocking);
        cudaEventCreateWithFlags(&eZ,    cudaEventDisableTiming);
        cudaEventCreateWithFlags(&eV,    cudaEventDisableTiming);
        cudaEventCreateWithFlags(&ePrep, cudaEventDisableTiming);
        cudaEventCreateWithFlags(&eJoin, cudaEventDisableTiming);
        cudaEventCreateWithFlags(&eFork, cudaEventDisableTiming);
    }

    cudaFuncSetAttribute(k_attn, cudaFuncAttributeMaxDynamicSharedMemorySize, SMEMSZ);

    void *p_hash, *p_accm, *p_accp, *p_rsum, *p_ne;
    cudaGetSymbolAddress(&p_hash, g_hash);
    cudaGetSymbolAddress(&p_accm, g_accm);
    cudaGetSymbolAddress(&p_accp, g_accp);
    cudaGetSymbolAddress(&p_rsum, g_rsum);
    cudaGetSymbolAddress(&p_ne,   g_ne);

    // fork s2/s3 from main so capture sees a rooted DAG
    cudaEventRecord(eFork, 0);
    cudaStreamWaitEvent(s2, eFork, 0);
    cudaStreamWaitEvent(s3, eFork, 0);

    // ---- s3: V transpose (needed only by k_attn) ----
    dim3 gv(NN / 32, 4);
    k_prepv<<<gv, 256, 0, s3>>>(mag, phase);
    cudaEventRecord(eV, s3);

    // ---- s2: accumulator zeroing (needed by attn+corr), then edge chain ----
    cudaMemsetAsync(p_accm, 0, NN * DD * sizeof(float), s2);
    cudaMemsetAsync(p_accp, 0, NN * DD * sizeof(float), s2);
    cudaMemsetAsync(p_rsum, 0, NN * sizeof(float), s2);
    cudaEventRecord(eZ, s2);
    cudaMemsetAsync(p_hash, 0xFF, HSIZE * sizeof(unsigned long long), s2);
    cudaMemsetAsync(p_ne,   0, sizeof(int), s2);
    k_wsum<<<1, 64, 0, s2>>>(W, b, (const unsigned*)ei);
    k_edge<<<EE / 256, 256, 0, s2>>>(ei, ea);
    k_compact<<<HSIZE / 512, 256, 0, s2>>>();

    // ---- main: G build; then attn once V + zeros are ready ----
    k_prep<<<NN / 8, 256>>>(mag, phase);
    cudaEventRecord(ePrep, 0);

    cudaStreamWaitEvent(s2, ePrep, 0);          // corr needs g_G/g_ediag
    k_corr<<<EE / 8, 256, 0, s2>>>(mag, phase);
    cudaEventRecord(eJoin, s2);

    cudaStreamWaitEvent(0, eZ, 0);
    cudaStreamWaitEvent(0, eV, 0);
    k_attn<<<256, 256, SMEMSZ>>>();

    // ---- join, then normalize ----
    cudaStreamWaitEvent(0, eJoin, 0);
    k_norm<<<NN / 4, 256>>>(mag, phase, out);
}